// round 15
// baseline (speedup 1.0000x reference)
#include <cuda_runtime.h>
#include <cuda_fp16.h>
#include <math.h>

#define NN   100000
#define NE   3200000
#define DIN  64
#define DH   40
#define DOUT 24

typedef unsigned long long ull;

// ---------------- scratch (static device globals; no allocation) -------------
// zero at module load; every call restores the zero state it consumes.
__device__ __align__(16) __half g_xlh[NN * DH];    // x @ W1_l^T (fp16 messages)
__device__ __align__(16) __half g_s1h[NN * DH];    // scatter sum layer 1
__device__ __align__(16) float  g_xr [NN * DH];    // x @ W1_r^T + b1
__device__ __align__(16) __half g_hlh[NN * DOUT];  // h @ W2_l^T (fp16 messages)
__device__ __align__(16) float  g_hr [NN * DOUT];  // h @ W2_r^T + b2
__device__ __align__(16) __half g_s2h[NN * DOUT];  // scatter sum layer 2
__device__ float g_cnt[NN];                        // in-degree

// ---------------- packed f32x2 helpers ----------------------------------------
__device__ __forceinline__ ull fma2(ull a, ull b, ull c) {
    ull d;
    asm("fma.rn.f32x2 %0, %1, %2, %3;" : "=l"(d) : "l"(a), "l"(b), "l"(c));
    return d;
}
__device__ __forceinline__ float hadd2(ull a) {
    float lo, hi;
    asm("mov.b64 {%0,%1}, %2;" : "=f"(lo), "=f"(hi) : "l"(a));
    return lo + hi;
}
__device__ __forceinline__ ull pack2(float lo, float hi) {
    ull r;
    asm("mov.b64 %0, {%1,%2};" : "=l"(r) : "f"(lo), "f"(hi));
    return r;
}

// ---------------- degree histogram (cnt zeroed by prev call's k_final) ---------
__global__ void k_hist(const int4* __restrict__ dst4) {
    int t = blockIdx.x * blockDim.x + threadIdx.x;
    int stride = gridDim.x * blockDim.x;
    for (int i = t; i < NE / 4; i += stride) {
        int4 d = dst4[i];
        asm volatile("red.global.add.f32 [%0], %1;" :: "l"(&g_cnt[d.x]), "f"(1.0f) : "memory");
        asm volatile("red.global.add.f32 [%0], %1;" :: "l"(&g_cnt[d.y]), "f"(1.0f) : "memory");
        asm volatile("red.global.add.f32 [%0], %1;" :: "l"(&g_cnt[d.z]), "f"(1.0f) : "memory");
        asm volatile("red.global.add.f32 [%0], %1;" :: "l"(&g_cnt[d.w]), "f"(1.0f) : "memory");
    }
}

// ---------------- xl = x @ W1_l^T  (64 -> 40), fp16 out (R10 structure) --------
__global__ __launch_bounds__(256) void k_gemm_xl(const float* __restrict__ x,
                                                 const float* __restrict__ W1l) {
    __shared__ ull sW[DH * DIN / 2];
    int tid = threadIdx.x;
    for (int i = tid; i < DH * DIN / 2; i += 256)
        sW[i] = ((const ull*)W1l)[i];
    __syncthreads();

    int n = blockIdx.x * 256 + tid;
    if (n >= NN) return;

    ull xr[DIN / 2];
    const ulonglong2* xp = (const ulonglong2*)(x + (size_t)n * DIN);
#pragma unroll
    for (int q = 0; q < DIN / 4; ++q) {
        ulonglong2 t = xp[q];
        xr[2 * q] = t.x; xr[2 * q + 1] = t.y;
    }
    __half2* orow = (__half2*)(g_xlh + (size_t)n * DH);
    for (int j = 0; j < DH; j += 2) {
        ull a0 = 0ull, a1 = 0ull;
        const ull* w0 = sW + j * (DIN / 2);
        const ull* w1 = w0 + (DIN / 2);
#pragma unroll
        for (int p = 0; p < DIN / 2; ++p) {
            a0 = fma2(xr[p], w0[p], a0);
            a1 = fma2(xr[p], w1[p], a1);
        }
        float2 o; o.x = hadd2(a0); o.y = hadd2(a1);
        orow[j / 2] = __float22half2_rn(o);
    }
}

// ---------------- xr = x @ W1_r^T + b1  (fp32 out; overlaps scatter1) ----------
__global__ __launch_bounds__(256) void k_gemm_rx(const float* __restrict__ x,
                                                 const float* __restrict__ W1r,
                                                 const float* __restrict__ b1) {
    __shared__ ull sW[DH * DIN / 2];
    __shared__ float sb[DH];
    int tid = threadIdx.x;
    for (int i = tid; i < DH * DIN / 2; i += 256)
        sW[i] = ((const ull*)W1r)[i];
    if (tid < DH) sb[tid] = b1[tid];
    __syncthreads();

    int n = blockIdx.x * 256 + tid;
    if (n >= NN) return;

    ull xr[DIN / 2];
    const ulonglong2* xp = (const ulonglong2*)(x + (size_t)n * DIN);
#pragma unroll
    for (int q = 0; q < DIN / 4; ++q) {
        ulonglong2 t = xp[q];
        xr[2 * q] = t.x; xr[2 * q + 1] = t.y;
    }
    float* orow = g_xr + (size_t)n * DH;
    for (int j = 0; j < DH; j += 2) {
        ull a0 = 0ull, a1 = 0ull;
        const ull* w0 = sW + j * (DIN / 2);
        const ull* w1 = w0 + (DIN / 2);
#pragma unroll
        for (int p = 0; p < DIN / 2; ++p) {
            a0 = fma2(xr[p], w0[p], a0);
            a1 = fma2(xr[p], w1[p], a1);
        }
        float2 o;
        o.x = hadd2(a0) + sb[j];
        o.y = hadd2(a1) + sb[j + 1];
        *(float2*)(orow + j) = o;
    }
}

// ---------------- scatter layer 1: s1h[dst] += xlh[src] (v4.f16x2 REDs) --------
// 5 threads per edge; grid*block == NE*5 exactly
__global__ void k_scatter1(const int* __restrict__ src, const int* __restrict__ dst) {
    unsigned t = blockIdx.x * blockDim.x + threadIdx.x;
    unsigned e = t / 5u, c = t - e * 5u;
    int s = src[e], d = dst[e];
    uint4 v = ((const uint4*)(g_xlh))[(size_t)s * 5 + c];   // row = 5 x 16B
    __half* p = g_s1h + (size_t)d * DH + c * 8;
    asm volatile("red.global.add.noftz.v4.f16x2 [%0], {%1,%2,%3,%4};"
                 :: "l"(p), "r"(v.x), "r"(v.y), "r"(v.z), "r"(v.w) : "memory");
}

// ---------------- combine + layer 2; re-zeroes own s1h row ---------------------
__global__ __launch_bounds__(256) void k_combine_l2(const float* __restrict__ W2l,
                                                    const float* __restrict__ W2r,
                                                    const float* __restrict__ b2) {
    __shared__ ull sWl[DOUT * DH / 2];
    __shared__ ull sWr[DOUT * DH / 2];
    __shared__ float sb2[DOUT];
    int tid = threadIdx.x;
    for (int i = tid; i < DOUT * DH / 2; i += 256) {
        sWl[i] = ((const ull*)W2l)[i];
        sWr[i] = ((const ull*)W2r)[i];
    }
    if (tid < DOUT) sb2[tid] = b2[tid];
    __syncthreads();

    int n = blockIdx.x * 256 + tid;
    if (n >= NN) return;

    float inv = __fdividef(1.f, fmaxf(g_cnt[n], 1.f));

    ull h2[DH / 2];
    __half2* s1p = (__half2*)(g_s1h + (size_t)n * DH);
    const float2* xrp = (const float2*)(g_xr + (size_t)n * DH);
#pragma unroll
    for (int q = 0; q < DH / 2; ++q) {
        float2 sres = __half22float2(s1p[q]);
        float2 rx = xrp[q];
        h2[q] = pack2(fmaxf(sres.x * inv + rx.x, 0.f),
                      fmaxf(sres.y * inv + rx.y, 0.f));
    }
    // restore zero state for next call (80B scatter1 touches)
    {
        uint4 z = make_uint4(0u, 0u, 0u, 0u);
        uint4* zp = (uint4*)s1p;
#pragma unroll
        for (int q = 0; q < 5; ++q) zp[q] = z;
    }

    __half2* ol = (__half2*)(g_hlh + (size_t)n * DOUT);
    float*  orr = g_hr + (size_t)n * DOUT;
    for (int j = 0; j < DOUT; j += 2) {
        ull al0 = 0ull, al1 = 0ull, ar0 = 0ull, ar1 = 0ull;
        const ull* wl0 = sWl + j * (DH / 2);
        const ull* wl1 = wl0 + (DH / 2);
        const ull* wr0 = sWr + j * (DH / 2);
        const ull* wr1 = wr0 + (DH / 2);
#pragma unroll
        for (int p = 0; p < DH / 2; ++p) {
            al0 = fma2(h2[p], wl0[p], al0);
            al1 = fma2(h2[p], wl1[p], al1);
            ar0 = fma2(h2[p], wr0[p], ar0);
            ar1 = fma2(h2[p], wr1[p], ar1);
        }
        float2 vl; vl.x = hadd2(al0); vl.y = hadd2(al1);
        float2 vr; vr.x = hadd2(ar0) + sb2[j]; vr.y = hadd2(ar1) + sb2[j + 1];
        ol[j / 2] = __float22half2_rn(vl);
        *(float2*)(orr + j) = vr;
    }
}

// ---------------- scatter layer 2: s2h[dst] += hlh[src] (v4.f16x2 REDs) --------
// 3 threads per edge; grid*block == NE*3 exactly
__global__ void k_scatter2(const int* __restrict__ src, const int* __restrict__ dst) {
    unsigned t = blockIdx.x * blockDim.x + threadIdx.x;
    unsigned e = t / 3u, c = t - e * 3u;
    int s = src[e], d = dst[e];
    uint4 v = ((const uint4*)(g_hlh))[(size_t)s * 3 + c];   // row = 3 x 16B
    __half* p = g_s2h + (size_t)d * DOUT + c * 8;
    asm volatile("red.global.add.noftz.v4.f16x2 [%0], {%1,%2,%3,%4};"
                 :: "l"(p), "r"(v.x), "r"(v.y), "r"(v.z), "r"(v.w) : "memory");
}

// ---------------- final: log_softmax; re-zeroes s2h row + cnt ------------------
__global__ void k_final(float* __restrict__ out) {
    int n = blockIdx.x * blockDim.x + threadIdx.x;
    if (n >= NN) return;
    float inv = __fdividef(1.f, fmaxf(g_cnt[n], 1.f));
    __half2* s2p = (__half2*)(g_s2h + (size_t)n * DOUT);
    const float4* hr4 = (const float4*)g_hr;
    float v[DOUT];
#pragma unroll
    for (int kk = 0; kk < 6; ++kk) {
        float4 b = hr4[(size_t)n * 6 + kk];
        float2 a0 = __half22float2(s2p[kk * 2]);
        float2 a1 = __half22float2(s2p[kk * 2 + 1]);
        v[kk * 4 + 0] = a0.x * inv + b.x;
        v[kk * 4 + 1] = a0.y * inv + b.y;
        v[kk * 4 + 2] = a1.x * inv + b.z;
        v[kk * 4 + 3] = a1.y * inv + b.w;
    }
    // restore zero state (48B scatter2 touches) + cnt
    {
        uint4 z = make_uint4(0u, 0u, 0u, 0u);
        uint4* zp = (uint4*)s2p;
#pragma unroll
        for (int q = 0; q < 3; ++q) zp[q] = z;
        g_cnt[n] = 0.f;
    }
    float m = v[0];
#pragma unroll
    for (int j = 1; j < DOUT; ++j) m = fmaxf(m, v[j]);
    float s = 0.f;
#pragma unroll
    for (int j = 0; j < DOUT; ++j) s += expf(v[j] - m);
    float l = m + logf(s);
    float4* o4 = (float4*)out;
#pragma unroll
    for (int kk = 0; kk < 6; ++kk) {
        float4 r;
        r.x = v[kk * 4 + 0] - l;
        r.y = v[kk * 4 + 1] - l;
        r.z = v[kk * 4 + 2] - l;
        r.w = v[kk * 4 + 3] - l;
        o4[(size_t)n * 6 + kk] = r;
    }
}

// ---------------- launch ----------------------------------------------------------
extern "C" void kernel_launch(void* const* d_in, const int* in_sizes, int n_in,
                              void* d_out, int out_size) {
    const float* x   = (const float*)d_in[0];
    const int*   ei  = (const int*)  d_in[1];
    const float* W1l = (const float*)d_in[2];
    const float* b1  = (const float*)d_in[3];
    const float* W1r = (const float*)d_in[4];
    const float* W2l = (const float*)d_in[5];
    const float* b2  = (const float*)d_in[6];
    const float* W2r = (const float*)d_in[7];
    float* out = (float*)d_out;

    const int* src = ei;
    const int* dst = ei + NE;
    const int4* dst4 = (const int4*)dst;

    const int nblk_node = (NN + 255) / 256;   // 391

    static cudaStream_t s2 = nullptr;
    static cudaEvent_t eFork = nullptr, eXL = nullptr, eRX = nullptr;
    if (s2 == nullptr) {
        cudaStreamCreateWithFlags(&s2, cudaStreamNonBlocking);
        cudaEventCreateWithFlags(&eFork, cudaEventDisableTiming);
        cudaEventCreateWithFlags(&eXL,   cudaEventDisableTiming);
        cudaEventCreateWithFlags(&eRX,   cudaEventDisableTiming);
    }

    // fork side stream
    cudaEventRecord(eFork, 0);
    cudaStreamWaitEvent(s2, eFork, 0);

    // side stream: layer-1 GEMMs (gemm_rx overlaps scatter1)
    k_gemm_xl<<<nblk_node, 256, 0, s2>>>(x, W1l);      // launch 0
    cudaEventRecord(eXL, s2);
    k_gemm_rx<<<nblk_node, 256, 0, s2>>>(x, W1r, b1);  // launch 1
    cudaEventRecord(eRX, s2);

    // main stream: histogram (cnt pre-zeroed by prior call / static init)
    k_hist<<<1024, 256>>>(dst4);                       // launch 2, ∥ gemm_xl
    cudaStreamWaitEvent(0, eXL, 0);
    k_scatter1<<<62500, 256>>>(src, dst);              // launch 3 (ncu slot), NE*5
    cudaStreamWaitEvent(0, eRX, 0);
    k_combine_l2<<<nblk_node, 256>>>(W2l, W2r, b2);    // launch 4
    k_scatter2<<<37500, 256>>>(src, dst);              // launch 5, NE*3
    k_final<<<(NN + 255) / 256, 256>>>(out);           // launch 6
}

// round 16
// speedup vs baseline: 1.0269x; 1.0269x over previous
#include <cuda_runtime.h>
#include <cuda_fp16.h>
#include <math.h>

#define NN   100000
#define NE   3200000
#define DIN  64
#define DH   40
#define DOUT 24

typedef unsigned long long ull;

// ---------------- scratch (static device globals; no allocation) -------------
// zero at module load; every call restores the zero state it consumes.
__device__ __align__(16) __half g_xlh[NN * DH];    // x @ W1_l^T (fp16 messages)
__device__ __align__(16) __half g_s1h[NN * DH];    // scatter sum layer 1
__device__ __align__(16) float  g_xr [NN * DH];    // x @ W1_r^T + b1
__device__ __align__(16) __half g_hlh[NN * DOUT];  // h @ W2_l^T (fp16 messages)
__device__ __align__(16) float  g_hr [NN * DOUT];  // h @ W2_r^T + b2
__device__ __align__(16) __half g_s2h[NN * DOUT];  // scatter sum layer 2
__device__ float g_cnt[NN];                        // in-degree

// ---------------- packed f32x2 helpers ----------------------------------------
__device__ __forceinline__ ull fma2(ull a, ull b, ull c) {
    ull d;
    asm("fma.rn.f32x2 %0, %1, %2, %3;" : "=l"(d) : "l"(a), "l"(b), "l"(c));
    return d;
}
__device__ __forceinline__ float hadd2(ull a) {
    float lo, hi;
    asm("mov.b64 {%0,%1}, %2;" : "=f"(lo), "=f"(hi) : "l"(a));
    return lo + hi;
}
__device__ __forceinline__ ull pack2(float lo, float hi) {
    ull r;
    asm("mov.b64 %0, {%1,%2};" : "=l"(r) : "f"(lo), "f"(hi));
    return r;
}

// ---------------- xl = x @ W1_l^T  (64 -> 40), fp16 out (R10 structure) --------
__global__ __launch_bounds__(256) void k_gemm_xl(const float* __restrict__ x,
                                                 const float* __restrict__ W1l) {
    __shared__ ull sW[DH * DIN / 2];
    int tid = threadIdx.x;
    for (int i = tid; i < DH * DIN / 2; i += 256)
        sW[i] = ((const ull*)W1l)[i];
    __syncthreads();

    int n = blockIdx.x * 256 + tid;
    if (n >= NN) return;

    ull xr[DIN / 2];
    const ulonglong2* xp = (const ulonglong2*)(x + (size_t)n * DIN);
#pragma unroll
    for (int q = 0; q < DIN / 4; ++q) {
        ulonglong2 t = xp[q];
        xr[2 * q] = t.x; xr[2 * q + 1] = t.y;
    }
    __half2* orow = (__half2*)(g_xlh + (size_t)n * DH);
    for (int j = 0; j < DH; j += 2) {
        ull a0 = 0ull, a1 = 0ull;
        const ull* w0 = sW + j * (DIN / 2);
        const ull* w1 = w0 + (DIN / 2);
#pragma unroll
        for (int p = 0; p < DIN / 2; ++p) {
            a0 = fma2(xr[p], w0[p], a0);
            a1 = fma2(xr[p], w1[p], a1);
        }
        float2 o; o.x = hadd2(a0); o.y = hadd2(a1);
        orow[j / 2] = __float22half2_rn(o);
    }
}

// ---------------- xr = x @ W1_r^T + b1  (fp32 out; overlaps scatter1) ----------
__global__ __launch_bounds__(256) void k_gemm_rx(const float* __restrict__ x,
                                                 const float* __restrict__ W1r,
                                                 const float* __restrict__ b1) {
    __shared__ ull sW[DH * DIN / 2];
    __shared__ float sb[DH];
    int tid = threadIdx.x;
    for (int i = tid; i < DH * DIN / 2; i += 256)
        sW[i] = ((const ull*)W1r)[i];
    if (tid < DH) sb[tid] = b1[tid];
    __syncthreads();

    int n = blockIdx.x * 256 + tid;
    if (n >= NN) return;

    ull xr[DIN / 2];
    const ulonglong2* xp = (const ulonglong2*)(x + (size_t)n * DIN);
#pragma unroll
    for (int q = 0; q < DIN / 4; ++q) {
        ulonglong2 t = xp[q];
        xr[2 * q] = t.x; xr[2 * q + 1] = t.y;
    }
    float* orow = g_xr + (size_t)n * DH;
    for (int j = 0; j < DH; j += 2) {
        ull a0 = 0ull, a1 = 0ull;
        const ull* w0 = sW + j * (DIN / 2);
        const ull* w1 = w0 + (DIN / 2);
#pragma unroll
        for (int p = 0; p < DIN / 2; ++p) {
            a0 = fma2(xr[p], w0[p], a0);
            a1 = fma2(xr[p], w1[p], a1);
        }
        float2 o;
        o.x = hadd2(a0) + sb[j];
        o.y = hadd2(a1) + sb[j + 1];
        *(float2*)(orow + j) = o;
    }
}

// ---------------- scatter layer 1: s1h[dst] += xlh[src], cnt[dst]+=1 ------------
// 5 threads per edge; grid*block == NE*5 exactly
__global__ void k_scatter1(const int* __restrict__ src, const int* __restrict__ dst) {
    unsigned t = blockIdx.x * blockDim.x + threadIdx.x;
    unsigned e = t / 5u, c = t - e * 5u;
    int s = src[e], d = dst[e];
    uint4 v = ((const uint4*)(g_xlh))[(size_t)s * 5 + c];   // row = 5 x 16B
    __half* p = g_s1h + (size_t)d * DH + c * 8;
    asm volatile("red.global.add.noftz.v4.f16x2 [%0], {%1,%2,%3,%4};"
                 :: "l"(p), "r"(v.x), "r"(v.y), "r"(v.z), "r"(v.w) : "memory");
    if (c == 0) {
        float* q = &g_cnt[d];
        asm volatile("red.global.add.f32 [%0], %1;" :: "l"(q), "f"(1.0f) : "memory");
    }
}

// ---------------- combine + layer 2; re-zeroes own s1h row ---------------------
__global__ __launch_bounds__(256) void k_combine_l2(const float* __restrict__ W2l,
                                                    const float* __restrict__ W2r,
                                                    const float* __restrict__ b2) {
    __shared__ ull sWl[DOUT * DH / 2];
    __shared__ ull sWr[DOUT * DH / 2];
    __shared__ float sb2[DOUT];
    int tid = threadIdx.x;
    for (int i = tid; i < DOUT * DH / 2; i += 256) {
        sWl[i] = ((const ull*)W2l)[i];
        sWr[i] = ((const ull*)W2r)[i];
    }
    if (tid < DOUT) sb2[tid] = b2[tid];
    __syncthreads();

    int n = blockIdx.x * 256 + tid;
    if (n >= NN) return;

    float inv = __fdividef(1.f, fmaxf(g_cnt[n], 1.f));

    ull h2[DH / 2];
    __half2* s1p = (__half2*)(g_s1h + (size_t)n * DH);
    const float2* xrp = (const float2*)(g_xr + (size_t)n * DH);
#pragma unroll
    for (int q = 0; q < DH / 2; ++q) {
        float2 sres = __half22float2(s1p[q]);
        float2 rx = xrp[q];
        h2[q] = pack2(fmaxf(sres.x * inv + rx.x, 0.f),
                      fmaxf(sres.y * inv + rx.y, 0.f));
    }
    // restore zero state for next call (80B scatter1 touches)
    {
        uint4 z = make_uint4(0u, 0u, 0u, 0u);
        uint4* zp = (uint4*)s1p;
#pragma unroll
        for (int q = 0; q < 5; ++q) zp[q] = z;
    }

    __half2* ol = (__half2*)(g_hlh + (size_t)n * DOUT);
    float*  orr = g_hr + (size_t)n * DOUT;
    for (int j = 0; j < DOUT; j += 2) {
        ull al0 = 0ull, al1 = 0ull, ar0 = 0ull, ar1 = 0ull;
        const ull* wl0 = sWl + j * (DH / 2);
        const ull* wl1 = wl0 + (DH / 2);
        const ull* wr0 = sWr + j * (DH / 2);
        const ull* wr1 = wr0 + (DH / 2);
#pragma unroll
        for (int p = 0; p < DH / 2; ++p) {
            al0 = fma2(h2[p], wl0[p], al0);
            al1 = fma2(h2[p], wl1[p], al1);
            ar0 = fma2(h2[p], wr0[p], ar0);
            ar1 = fma2(h2[p], wr1[p], ar1);
        }
        float2 vl; vl.x = hadd2(al0); vl.y = hadd2(al1);
        float2 vr; vr.x = hadd2(ar0) + sb2[j]; vr.y = hadd2(ar1) + sb2[j + 1];
        ol[j / 2] = __float22half2_rn(vl);
        *(float2*)(orr + j) = vr;
    }
}

// ---------------- scatter layer 2: s2h[dst] += hlh[src] (v4.f16x2 REDs) --------
// 3 threads per edge; grid*block == NE*3 exactly
__global__ void k_scatter2(const int* __restrict__ src, const int* __restrict__ dst) {
    unsigned t = blockIdx.x * blockDim.x + threadIdx.x;
    unsigned e = t / 3u, c = t - e * 3u;
    int s = src[e], d = dst[e];
    uint4 v = ((const uint4*)(g_hlh))[(size_t)s * 3 + c];   // row = 3 x 16B
    __half* p = g_s2h + (size_t)d * DOUT + c * 8;
    asm volatile("red.global.add.noftz.v4.f16x2 [%0], {%1,%2,%3,%4};"
                 :: "l"(p), "r"(v.x), "r"(v.y), "r"(v.z), "r"(v.w) : "memory");
}

// ---------------- final: log_softmax; re-zeroes s2h row + cnt ------------------
__global__ void k_final(float* __restrict__ out) {
    int n = blockIdx.x * blockDim.x + threadIdx.x;
    if (n >= NN) return;
    float inv = __fdividef(1.f, fmaxf(g_cnt[n], 1.f));
    __half2* s2p = (__half2*)(g_s2h + (size_t)n * DOUT);
    const float4* hr4 = (const float4*)g_hr;
    float v[DOUT];
#pragma unroll
    for (int kk = 0; kk < 6; ++kk) {
        float4 b = hr4[(size_t)n * 6 + kk];
        float2 a0 = __half22float2(s2p[kk * 2]);
        float2 a1 = __half22float2(s2p[kk * 2 + 1]);
        v[kk * 4 + 0] = a0.x * inv + b.x;
        v[kk * 4 + 1] = a0.y * inv + b.y;
        v[kk * 4 + 2] = a1.x * inv + b.z;
        v[kk * 4 + 3] = a1.y * inv + b.w;
    }
    // restore zero state (48B scatter2 touches) + cnt
    {
        uint4 z = make_uint4(0u, 0u, 0u, 0u);
        uint4* zp = (uint4*)s2p;
#pragma unroll
        for (int q = 0; q < 3; ++q) zp[q] = z;
        g_cnt[n] = 0.f;
    }
    float m = v[0];
#pragma unroll
    for (int j = 1; j < DOUT; ++j) m = fmaxf(m, v[j]);
    float s = 0.f;
#pragma unroll
    for (int j = 0; j < DOUT; ++j) s += expf(v[j] - m);
    float l = m + logf(s);
    float4* o4 = (float4*)out;
#pragma unroll
    for (int kk = 0; kk < 6; ++kk) {
        float4 r;
        r.x = v[kk * 4 + 0] - l;
        r.y = v[kk * 4 + 1] - l;
        r.z = v[kk * 4 + 2] - l;
        r.w = v[kk * 4 + 3] - l;
        o4[(size_t)n * 6 + kk] = r;
    }
}

// ---------------- launch ----------------------------------------------------------
extern "C" void kernel_launch(void* const* d_in, const int* in_sizes, int n_in,
                              void* d_out, int out_size) {
    const float* x   = (const float*)d_in[0];
    const int*   ei  = (const int*)  d_in[1];
    const float* W1l = (const float*)d_in[2];
    const float* b1  = (const float*)d_in[3];
    const float* W1r = (const float*)d_in[4];
    const float* W2l = (const float*)d_in[5];
    const float* b2  = (const float*)d_in[6];
    const float* W2r = (const float*)d_in[7];
    float* out = (float*)d_out;

    const int* src = ei;
    const int* dst = ei + NE;

    const int nblk_node = (NN + 255) / 256;   // 391

    static cudaStream_t s2 = nullptr;
    static cudaEvent_t eFork = nullptr, eXL = nullptr, eRX = nullptr;
    if (s2 == nullptr) {
        cudaStreamCreateWithFlags(&s2, cudaStreamNonBlocking);
        cudaEventCreateWithFlags(&eFork, cudaEventDisableTiming);
        cudaEventCreateWithFlags(&eXL,   cudaEventDisableTiming);
        cudaEventCreateWithFlags(&eRX,   cudaEventDisableTiming);
    }

    // fork side stream
    cudaEventRecord(eFork, 0);
    cudaStreamWaitEvent(s2, eFork, 0);

    // side stream: layer-1 GEMMs (gemm_rx overlaps scatter1)
    k_gemm_xl<<<nblk_node, 256, 0, s2>>>(x, W1l);      // launch 0
    cudaEventRecord(eXL, s2);
    k_gemm_rx<<<nblk_node, 256, 0, s2>>>(x, W1r, b1);  // launch 1
    cudaEventRecord(eRX, s2);

    // main stream (buffers pre-zeroed: static init / previous call's cleanup)
    cudaStreamWaitEvent(0, eXL, 0);
    k_scatter1<<<62500, 256>>>(src, dst);              // launch 2, NE*5
    cudaStreamWaitEvent(0, eRX, 0);
    k_combine_l2<<<nblk_node, 256>>>(W2l, W2r, b2);    // launch 3 (ncu slot)
    k_scatter2<<<37500, 256>>>(src, dst);              // launch 4, NE*3
    k_final<<<(NN + 255) / 256, 256>>>(out);           // launch 5
}